// round 5
// baseline (speedup 1.0000x reference)
#include <cuda_runtime.h>
#include <cstdint>

// CausalWindowedAttention: B=2,H=16,S=2048,D=64, window=256, temp=8
// Output = concat(out[B,H,S,D], attn[B,H,S,S]) as float32.
// attn rows written via cp.async.bulk: zero prefix/suffix from a zero SMEM
// buffer (issued early), band segment from the score buffer after softmax.
// 1024 threads/CTA for latency hiding (single CTA/SM due to 204KB smem).

#define SQ    2048
#define DH    64
#define MT    64              // queries per CTA tile
#define WIN   256
#define KR    320             // valid key rows for the tile window union
#define KRA   352             // allocated key rows (zero-padded tail)
#define KPAD  68              // padded K/V row (floats)
#define SROW  328             // score row stride: 4 slack + up to 324 offsets
#define NTH   1024

// smem layout (floats)
#define SM_Q   0
#define SM_K   (MT * DH)                  // 4096
#define SM_S   (SM_K + KRA * KPAD)        // 28032
#define SM_Z   (SM_S + MT * SROW)         // 49024
#define SM_TOT (SM_Z + 2048)              // 51072 floats = 204288 B

__device__ __forceinline__ void ffma2(unsigned long long& d,
                                      unsigned long long a,
                                      unsigned long long b) {
    asm("fma.rn.f32x2 %0, %1, %2, %0;" : "+l"(d) : "l"(a), "l"(b));
}
__device__ __forceinline__ unsigned long long pk2(float x) {
    unsigned long long r;
    asm("mov.b64 %0, {%1, %1};" : "=l"(r) : "f"(x));
    return r;
}
__device__ __forceinline__ float unpk_sum(unsigned long long a) {
    float lo, hi;
    asm("mov.b64 {%0, %1}, %2;" : "=f"(lo), "=f"(hi) : "l"(a));
    return lo + hi;
}
__device__ __forceinline__ uint32_t s2u(const void* p) {
    return (uint32_t)__cvta_generic_to_shared(p);
}
__device__ __forceinline__ void bulk_store(void* gdst, uint32_t ssrc, uint32_t bytes) {
    asm volatile("cp.async.bulk.global.shared::cta.bulk_group [%0], [%1], %2;"
                 :: "l"(gdst), "r"(ssrc), "r"(bytes) : "memory");
}
__device__ __forceinline__ void fence_async() {
    asm volatile("fence.proxy.async.shared::cta;" ::: "memory");
}

__global__ void __launch_bounds__(NTH, 1)
cwa_kernel(const float* __restrict__ q,
           const float* __restrict__ k,
           const float* __restrict__ v,
           float* __restrict__ out,    // [BH, SQ, DH]
           float* __restrict__ attn)   // [BH, SQ, SQ]
{
    extern __shared__ float sm[];
    float* sQ = sm + SM_Q;
    float* sK = sm + SM_K;   // reused for V later
    float* sS = sm + SM_S;   // 64 rows x SROW; row m offsets indexed [-4, 324)
    float* sZ = sm + SM_Z;   // 2048 zero floats

    const int tile = blockIdx.x;
    const int bh   = blockIdx.y;
    const int i0   = tile * MT;
    const int tid  = threadIdx.x;
    const int lane = tid & 31;
    const int w    = tid >> 5;           // 0..31

    const size_t base = (size_t)bh * SQ * DH;
    const size_t attn_base = (size_t)bh * SQ * SQ;
    const int jn0 = i0 - (WIN - 1);      // key j for smem key-row n: j = jn0 + n

    // ---- load Q tile (64 x 64) ----
    {
        const float4* qg = (const float4*)(q + base + (size_t)i0 * DH);
        float4* qs = (float4*)sQ;
        for (int idx = tid; idx < MT * (DH / 4); idx += NTH)
            qs[idx] = qg[idx];
    }
    // ---- load K window (352 rows, zero-fill OOB) ----
    for (int idx = tid; idx < KRA * (DH / 4); idx += NTH) {
        int n = idx >> 4;
        int c = idx & 15;
        int j = jn0 + n;
        float4 val = make_float4(0.f, 0.f, 0.f, 0.f);
        if (j >= 0 && j < SQ)
            val = *(const float4*)(k + base + (size_t)j * DH + c * 4);
        *(float4*)&sK[n * KPAD + c * 4] = val;
    }
    // ---- zero buffer ----
    {
        float4* zs = (float4*)sZ;
        const float4 z4 = make_float4(0.f, 0.f, 0.f, 0.f);
        for (int idx = tid; idx < 2048 / 4; idx += NTH)
            zs[idx] = z4;
    }
    __syncthreads();

    // ---- issue zero prefix/suffix bulk stores for all 64 rows NOW ----
    if (tid < MT) {
        const int m = tid;
        const int i = i0 + m;
        const int jlo = max(0, i - (WIN - 1));
        const int jstart4 = jlo & ~3;
        const int jend4 = (i + 4) & ~3;           // exclusive, multiple of 4
        float* dst = attn + attn_base + (size_t)i * SQ;
        const uint32_t zaddr = s2u(sZ);
        fence_async();
        const uint32_t pb = (uint32_t)jstart4 * 4u;
        if (pb) bulk_store(dst, zaddr, pb);
        const uint32_t sb = (uint32_t)(SQ - jend4) * 4u;
        if (sb) bulk_store(dst + jend4, zaddr, sb);
    }

    // ---- scores: warp w -> rows m0, m0+1; keys n = m0 + lane + 32*ni, ni<9.
    //      Row m storage: sS[m*SROW + 4 + off], off = n - s[mi].
    const int m0 = w * 2;
    int srow_s[2];       // s[mi] = (jlo(m) & ~3) - jn0
    {
        #pragma unroll
        for (int mi = 0; mi < 2; mi++) {
            const int i = i0 + m0 + mi;
            const int jlo = max(0, i - (WIN - 1));
            srow_s[mi] = (jlo & ~3) - jn0;
        }

        unsigned long long acc[2][9];
        #pragma unroll
        for (int mi = 0; mi < 2; mi++)
            #pragma unroll
            for (int ni = 0; ni < 9; ni++)
                acc[mi][ni] = 0ULL;

        const int nbase = (m0 + lane) * KPAD;

        #pragma unroll 1
        for (int dc = 0; dc < DH / 4; dc++) {
            ulonglong2 q2a = *(const ulonglong2*)&sQ[(m0 + 0) * DH + dc * 4];
            ulonglong2 q2b = *(const ulonglong2*)&sQ[(m0 + 1) * DH + dc * 4];
            #pragma unroll
            for (int ni = 0; ni < 9; ni++) {
                ulonglong2 k2 = *(const ulonglong2*)&sK[nbase + ni * 32 * KPAD + dc * 4];
                ffma2(acc[0][ni], q2a.x, k2.x);
                ffma2(acc[0][ni], q2a.y, k2.y);
                ffma2(acc[1][ni], q2b.x, k2.x);
                ffma2(acc[1][ni], q2b.y, k2.y);
            }
        }
        #pragma unroll
        for (int mi = 0; mi < 2; mi++) {
            float* rp = sS + (m0 + mi) * SROW + 4;
            #pragma unroll
            for (int ni = 0; ni < 9; ni++) {
                const int n = m0 + lane + 32 * ni;
                const int off = n - srow_s[mi];
                if ((unsigned)(off + 4) < (unsigned)SROW)
                    rp[off] = unpk_sum(acc[mi][ni]) * 0.125f;  // 1/temperature
            }
        }
    }
    // (scores for this warp's rows are warp-local: no CTA sync needed)

    // ---- softmax per row (warp owns rows m0, m0+1); zero-fill outside band ----
    {
        #pragma unroll 1
        for (int r = 0; r < 2; r++) {
            const int m = m0 + r;
            const int i = i0 + m;
            const int jlo = max(0, i - (WIN - 1));
            const int off_lo = jlo & 3;
            const int off_hi = i - (jlo & ~3);
            float* rp = sS + m * SROW + 4;

            float mx = -1e30f;
            for (int off = off_lo + lane; off <= off_hi; off += 32)
                mx = fmaxf(mx, rp[off]);
            #pragma unroll
            for (int o = 16; o; o >>= 1)
                mx = fmaxf(mx, __shfl_xor_sync(0xffffffffu, mx, o));

            float sum = 0.f;
            for (int off = off_lo + lane; off <= off_hi; off += 32) {
                float e = __expf(rp[off] - mx);
                rp[off] = e;
                sum += e;
            }
            #pragma unroll
            for (int o = 16; o; o >>= 1)
                sum += __shfl_xor_sync(0xffffffffu, sum, o);

            const float inv = 1.f / sum;
            for (int off = -4 + lane; off < SROW - 4; off += 32) {
                float val = (off >= off_lo && off <= off_hi) ? rp[off] * inv : 0.f;
                rp[off] = val;
            }
        }
    }

    // ---- issue this warp's band bulk stores immediately (overlaps others) ----
    __syncwarp();
    if (lane < 2) {
        const int m = m0 + lane;
        const int i = i0 + m;
        const int jlo = max(0, i - (WIN - 1));
        const int jstart4 = jlo & ~3;
        const int jend4 = (i + 4) & ~3;
        fence_async();
        bulk_store(attn + attn_base + (size_t)i * SQ + jstart4,
                   s2u(sS + m * SROW + 4),
                   (uint32_t)(jend4 - jstart4) * 4u);
    }

    __syncthreads();   // all QK reads of sK done before V overwrites it

    // ---- load V into the K buffer ----
    for (int idx = tid; idx < KR * (DH / 4); idx += NTH) {
        int n = idx >> 4;
        int c = idx & 15;
        int j = jn0 + n;
        float4 val = make_float4(0.f, 0.f, 0.f, 0.f);
        if (j >= 0 && j < SQ)
            val = *(const float4*)(v + base + (size_t)j * DH + c * 4);
        *(float4*)&sK[n * KPAD + c * 4] = val;
    }
    __syncthreads();

    // ---- PV: thread owns 1 row x 1 d-quad; loop bound warp-uniform ----
    {
        const int dq = tid & 15;          // d cols dq*4..dq*4+3
        const int r  = tid >> 4;          // row 0..63 (warp w covers rows 2w,2w+1)
        const int i  = i0 + r;
        const int jlo = max(0, i - (WIN - 1));
        const int s_r = (jlo & ~3) - jn0;

        // rp[n] reads offset (n - s_r) of row r; defined (zero) on [-4, 324)
        const float* rp = sS + r * SROW + 4 - s_r;

        const int nw_base = m0;                        // warp-uniform row base
        const int nlo_cta = max(0, -jn0);
        const int n_start = max(nw_base, nlo_cta);     // warp-uniform
        const int n_end   = nw_base + 257;             // warp-uniform, inclusive

        unsigned long long ax = 0ULL, az = 0ULL;

        #pragma unroll 4
        for (int n = n_start; n <= n_end; n++) {
            ulonglong2 v2 = *(const ulonglong2*)&sK[n * KPAD + dq * 4];
            unsigned long long p = pk2(rp[n]);
            ffma2(ax, p, v2.x);
            ffma2(az, p, v2.y);
        }

        ulonglong2 o;
        o.x = ax; o.y = az;
        *(ulonglong2*)(out + base + (size_t)i * DH + dq * 4) = o;
    }

    // ---- ensure all bulk stores complete before kernel end ----
    asm volatile("cp.async.bulk.commit_group;" ::: "memory");
    asm volatile("cp.async.bulk.wait_group 0;" ::: "memory");
}

extern "C" void kernel_launch(void* const* d_in, const int* in_sizes, int n_in,
                              void* d_out, int out_size)
{
    const float* q = (const float*)d_in[0];
    const float* k = (const float*)d_in[1];
    const float* v = (const float*)d_in[2];

    const int BH = in_sizes[0] / (SQ * DH);   // 32

    float* out  = (float*)d_out;
    float* attn = out + (size_t)BH * SQ * DH;

    cudaFuncSetAttribute(cwa_kernel,
                         cudaFuncAttributeMaxDynamicSharedMemorySize,
                         SM_TOT * (int)sizeof(float));

    dim3 grid(SQ / MT, BH);
    cwa_kernel<<<grid, NTH, SM_TOT * sizeof(float)>>>(q, k, v, out, attn);
    (void)n_in; (void)out_size;
}

// round 7
// speedup vs baseline: 1.2060x; 1.2060x over previous
#include <cuda_runtime.h>
#include <cstdint>

// CausalWindowedAttention: B=2,H=16,S=2048,D=64, window=256, temp=8
// Output = concat(out[B,H,S,D], attn[B,H,S,S]) as float32.
// attn written via cp.async.bulk: zeros early (overlap QK/softmax), band after
// softmax. Q/K/V loaded with cp.async; V issued early to drain under softmax.
// PV uses float4 probability loads (rows padded+aligned so n%4==3 vector
// starts are 16B aligned).

#define SQ    2048
#define DH    64
#define MT    64              // queries per CTA tile
#define WIN   256
#define KR    320             // valid key rows for the tile window union
#define KRA   352             // allocated key rows (zero-padded tail)
#define KPAD  68              // padded K/V row (floats)
#define SROW  328             // score row stride: 4 slack + up to 324 offsets
#define NTH   512

// smem layout (floats)
#define SM_Q   0
#define SM_K   (MT * DH)                  // 4096
#define SM_S   (SM_K + KRA * KPAD)        // 28032
#define SM_Z   (SM_S + MT * SROW)         // 49024
#define SM_TOT (SM_Z + 2048)              // 51072 floats = 204288 B

typedef unsigned long long ull;

__device__ __forceinline__ void ffma2(ull& d, ull a, ull b) {
    asm("fma.rn.f32x2 %0, %1, %2, %0;" : "+l"(d) : "l"(a), "l"(b));
}
__device__ __forceinline__ ull pk2(float x) {
    ull r;
    asm("mov.b64 %0, {%1, %1};" : "=l"(r) : "f"(x));
    return r;
}
__device__ __forceinline__ float unpk_sum(ull a) {
    float lo, hi;
    asm("mov.b64 {%0, %1}, %2;" : "=f"(lo), "=f"(hi) : "l"(a));
    return lo + hi;
}
__device__ __forceinline__ uint32_t s2u(const void* p) {
    return (uint32_t)__cvta_generic_to_shared(p);
}
__device__ __forceinline__ void bulk_store(void* gdst, uint32_t ssrc, uint32_t bytes) {
    asm volatile("cp.async.bulk.global.shared::cta.bulk_group [%0], [%1], %2;"
                 :: "l"(gdst), "r"(ssrc), "r"(bytes) : "memory");
}
__device__ __forceinline__ void fence_async() {
    asm volatile("fence.proxy.async.shared::cta;" ::: "memory");
}
__device__ __forceinline__ void cp16(uint32_t sdst, const void* gsrc, uint32_t sz) {
    asm volatile("cp.async.cg.shared.global [%0], [%1], 16, %2;"
                 :: "r"(sdst), "l"(gsrc), "r"(sz) : "memory");
}
__device__ __forceinline__ void cp_commit() {
    asm volatile("cp.async.commit_group;" ::: "memory");
}
__device__ __forceinline__ void cp_wait0() {
    asm volatile("cp.async.wait_group 0;" ::: "memory");
}

__global__ void __launch_bounds__(NTH, 1)
cwa_kernel(const float* __restrict__ q,
           const float* __restrict__ k,
           const float* __restrict__ v,
           float* __restrict__ out,    // [BH, SQ, DH]
           float* __restrict__ attn)   // [BH, SQ, SQ]
{
    extern __shared__ float sm[];
    float* sQ = sm + SM_Q;
    float* sK = sm + SM_K;   // reused for V
    float* sS = sm + SM_S;   // 64 rows x SROW; row m offsets indexed [-4, 324)
    float* sZ = sm + SM_Z;   // 2048 zero floats

    const int tile = blockIdx.x;
    const int bh   = blockIdx.y;
    const int i0   = tile * MT;
    const int tid  = threadIdx.x;
    const int lane = tid & 31;
    const int w    = tid >> 5;           // 0..15

    const size_t base = (size_t)bh * SQ * DH;
    const size_t attn_base = (size_t)bh * SQ * SQ;
    const int jn0 = i0 - (WIN - 1);      // key j for smem key-row n: j = jn0 + n

    // ---- zero buffer for TMA zero stores ----
    {
        float4* zs = (float4*)sZ;
        const float4 z4 = make_float4(0.f, 0.f, 0.f, 0.f);
        for (int idx = tid; idx < 2048 / 4; idx += NTH)
            zs[idx] = z4;
    }
    // ---- Q tile via cp.async (contiguous, always in-bounds) ----
    {
        const float4* qg = (const float4*)(q + base + (size_t)i0 * DH);
        for (int idx = tid; idx < MT * (DH / 4); idx += NTH)
            cp16(s2u((float4*)sQ + idx), qg + idx, 16);
    }
    // ---- K window via cp.async (zero-fill OOB via src_size=0) ----
    for (int idx = tid; idx < KRA * (DH / 4); idx += NTH) {
        int n = idx >> 4;
        int c = idx & 15;
        int j = jn0 + n;
        bool valid = (j >= 0 && j < SQ);
        const float* src = valid ? (k + base + (size_t)j * DH + c * 4) : (k + base);
        cp16(s2u(&sK[n * KPAD + c * 4]), src, valid ? 16u : 0u);
    }
    cp_commit();
    __syncthreads();    // sZ visible CTA-wide

    // ---- issue zero prefix/suffix bulk stores for all 64 rows NOW:
    //      independent of all compute; DRAM write stream drains under QK.
    if (tid < MT) {
        const int m = tid;
        const int i = i0 + m;
        const int jlo = max(0, i - (WIN - 1));
        const int jstart4 = jlo & ~3;
        const int jend4 = (i + 4) & ~3;           // exclusive, multiple of 4
        float* dst = attn + attn_base + (size_t)i * SQ;
        const uint32_t zaddr = s2u(sZ);
        fence_async();
        const uint32_t pb = (uint32_t)jstart4 * 4u;
        if (pb) bulk_store(dst, zaddr, pb);
        const uint32_t sb = (uint32_t)(SQ - jend4) * 4u;
        if (sb) bulk_store(dst + jend4, zaddr, sb);
    }

    cp_wait0();
    __syncthreads();    // Q, K resident

    // ---- QK: warp w -> rows m0..m0+3, keys n = m0 + lane + 32*ni, ni<9 ----
    const int m0 = w * 4;
    int srow_s[4];       // s[mi] = (jlo(m) & ~3) - jn0   (each ≡ 3 mod 4)
    #pragma unroll
    for (int mi = 0; mi < 4; mi++) {
        const int i = i0 + m0 + mi;
        const int jlo = max(0, i - (WIN - 1));
        srow_s[mi] = (jlo & ~3) - jn0;
    }
    {
        ull acc[4][9];
        #pragma unroll
        for (int mi = 0; mi < 4; mi++)
            #pragma unroll
            for (int ni = 0; ni < 9; ni++)
                acc[mi][ni] = 0ULL;

        int nb[9];
        #pragma unroll
        for (int ni = 0; ni < 9; ni++)
            nb[ni] = (m0 + lane + 32 * ni) * KPAD;

        #pragma unroll 1
        for (int dc = 0; dc < DH / 4; dc++) {
            ulonglong2 q2[4];
            #pragma unroll
            for (int mi = 0; mi < 4; mi++)
                q2[mi] = *(const ulonglong2*)&sQ[(m0 + mi) * DH + dc * 4];
            #pragma unroll
            for (int ni = 0; ni < 9; ni++) {
                ulonglong2 k2 = *(const ulonglong2*)&sK[nb[ni] + dc * 4];
                #pragma unroll
                for (int mi = 0; mi < 4; mi++) {
                    ffma2(acc[mi][ni], q2[mi].x, k2.x);
                    ffma2(acc[mi][ni], q2[mi].y, k2.y);
                }
            }
        }
        #pragma unroll
        for (int mi = 0; mi < 4; mi++) {
            float* rp = sS + (m0 + mi) * SROW + 4;
            #pragma unroll
            for (int ni = 0; ni < 9; ni++) {
                const int off = m0 + lane + 32 * ni - srow_s[mi];
                if ((unsigned)(off + 4) < (unsigned)SROW)
                    rp[off] = unpk_sum(acc[mi][ni]) * 0.125f;  // 1/temperature
            }
        }
    }
    __syncthreads();   // all warps done reading sK (scores are warp-local)

    // ---- V via cp.async into sK: drains under softmax ----
    for (int idx = tid; idx < KR * (DH / 4); idx += NTH) {
        int n = idx >> 4;
        int c = idx & 15;
        int j = jn0 + n;
        bool valid = (j >= 0 && j < SQ);
        const float* src = valid ? (v + base + (size_t)j * DH + c * 4) : (v + base);
        cp16(s2u(&sK[n * KPAD + c * 4]), src, valid ? 16u : 0u);
    }
    cp_commit();

    // ---- softmax: warp w owns rows m0..m0+3; zero-fill outside band ----
    {
        #pragma unroll 1
        for (int r = 0; r < 4; r++) {
            const int m = m0 + r;
            const int i = i0 + m;
            const int jlo = max(0, i - (WIN - 1));
            const int off_lo = jlo & 3;
            const int off_hi = i - (jlo & ~3);
            float* rp = sS + m * SROW + 4;

            float mx = -1e30f;
            for (int off = off_lo + lane; off <= off_hi; off += 32)
                mx = fmaxf(mx, rp[off]);
            #pragma unroll
            for (int o = 16; o; o >>= 1)
                mx = fmaxf(mx, __shfl_xor_sync(0xffffffffu, mx, o));

            float sum = 0.f;
            for (int off = off_lo + lane; off <= off_hi; off += 32) {
                float e = __expf(rp[off] - mx);
                rp[off] = e;
                sum += e;
            }
            #pragma unroll
            for (int o = 16; o; o >>= 1)
                sum += __shfl_xor_sync(0xffffffffu, sum, o);

            const float inv = 1.f / sum;
            for (int off = -4 + lane; off < SROW - 4; off += 32) {
                float val = (off >= off_lo && off <= off_hi) ? rp[off] * inv : 0.f;
                rp[off] = val;
            }
        }
    }

    // ---- issue this warp's band bulk stores (rows are warp-local) ----
    __syncwarp();
    if (lane < 4) {
        const int m = m0 + lane;
        const int i = i0 + m;
        const int jlo = max(0, i - (WIN - 1));
        const int jstart4 = jlo & ~3;
        const int jend4 = (i + 4) & ~3;
        fence_async();
        bulk_store(attn + attn_base + (size_t)i * SQ + jstart4,
                   s2u(sS + m * SROW + 4),
                   (uint32_t)(jend4 - jstart4) * 4u);
    }

    cp_wait0();        // V resident
    __syncthreads();   // all softmax rows + V visible for PV

    // ---- PV: thread owns rows {2mg, 2mg+1} x d-quad dq; float4 p loads ----
    {
        const int dq = tid & 15;          // d cols dq*4..dq*4+3
        const int mg = tid >> 4;          // 0..31
        const int r0 = 2 * mg;
        const int r1 = r0 + 1;
        const int w4 = (tid >> 5) * 4;    // warp-uniform row base (= m0)

        const int s0 = ((max(0, i0 + r0 - (WIN - 1))) & ~3) - jn0;
        const int s1 = ((max(0, i0 + r1 - (WIN - 1))) & ~3) - jn0;
        const int smax = ((max(0, i0 + w4 + 3 - (WIN - 1))) & ~3) - jn0;

        const int nbase = smax - 4;             // ≡ 3 (mod 4): aligned p4 loads
        const int nend  = w4 + 258;             // inclusive; (nend-nbase+1)%4==0
        const int iters = (nend - nbase + 1) >> 2;

        const float* rp0 = sS + r0 * SROW + 4 - s0;   // rp0[n], zero outside band
        const float* rp1 = sS + r1 * SROW + 4 - s1;

        ull ax0 = 0ULL, az0 = 0ULL, ax1 = 0ULL, az1 = 0ULL;

        int n = nbase;
        #pragma unroll 1
        for (int it = 0; it < iters; it++, n += 4) {
            const float4 p0 = *(const float4*)&rp0[n];
            const float4 p1 = *(const float4*)&rp1[n];
            #pragma unroll
            for (int c = 0; c < 4; c++) {
                ulonglong2 v2 = *(const ulonglong2*)&sK[(n + c) * KPAD + dq * 4];
                ull pc0 = pk2((&p0.x)[c]);
                ull pc1 = pk2((&p1.x)[c]);
                ffma2(ax0, pc0, v2.x);
                ffma2(az0, pc0, v2.y);
                ffma2(ax1, pc1, v2.x);
                ffma2(az1, pc1, v2.y);
            }
        }

        ulonglong2 o0; o0.x = ax0; o0.y = az0;
        ulonglong2 o1; o1.x = ax1; o1.y = az1;
        *(ulonglong2*)(out + base + (size_t)(i0 + r0) * DH + dq * 4) = o0;
        *(ulonglong2*)(out + base + (size_t)(i0 + r1) * DH + dq * 4) = o1;
    }

    // ---- ensure all bulk stores complete before kernel end ----
    asm volatile("cp.async.bulk.commit_group;" ::: "memory");
    asm volatile("cp.async.bulk.wait_group 0;" ::: "memory");
}

extern "C" void kernel_launch(void* const* d_in, const int* in_sizes, int n_in,
                              void* d_out, int out_size)
{
    const float* q = (const float*)d_in[0];
    const float* k = (const float*)d_in[1];
    const float* v = (const float*)d_in[2];

    const int BH = in_sizes[0] / (SQ * DH);   // 32

    float* out  = (float*)d_out;
    float* attn = out + (size_t)BH * SQ * DH;

    cudaFuncSetAttribute(cwa_kernel,
                         cudaFuncAttributeMaxDynamicSharedMemorySize,
                         SM_TOT * (int)sizeof(float));

    dim3 grid(SQ / MT, BH);
    cwa_kernel<<<grid, NTH, SM_TOT * sizeof(float)>>>(q, k, v, out, attn);
    (void)n_in; (void)out_size;
}

// round 8
// speedup vs baseline: 1.4609x; 1.2114x over previous
#include <cuda_runtime.h>
#include <cstdint>

// CausalWindowedAttention: B=2,H=16,S=2048,D=64, window=256, temp=8
// Output = concat(out[B,H,S,D], attn[B,H,S,S]) as float32.
// attn written via cp.async.bulk: zeros early (overlap QK), band after the
// fused QK+softmax epilogue (softmax done in registers; sS pre-zeroed).
// PV: thread owns 4 rows x 1 d-quad x half keys; partials combined via sQ.

#define SQ    2048
#define DH    64
#define MT    64              // queries per CTA tile
#define WIN   256
#define KR    320             // valid key rows for the tile window union
#define KRA   352             // allocated key rows (zero-padded tail)
#define KPAD  68              // padded K/V row (floats), conflict-free LDS.128
#define SROW  268             // score row stride: 4 slack + up to 264 offsets
#define NTH   512

// smem layout (floats)
#define SM_Q   0
#define SM_K   (MT * DH)                  // 4096
#define SM_S   (SM_K + KRA * KPAD)        // 28032
#define SM_Z   (SM_S + MT * SROW)         // 45184
#define SM_TOT (SM_Z + 2048)              // 47232 floats = 188928 B

typedef unsigned long long ull;

__device__ __forceinline__ void ffma2(ull& d, ull a, ull b) {
    asm("fma.rn.f32x2 %0, %1, %2, %0;" : "+l"(d) : "l"(a), "l"(b));
}
__device__ __forceinline__ ull pk2(float x) {
    ull r;
    asm("mov.b64 %0, {%1, %1};" : "=l"(r) : "f"(x));
    return r;
}
__device__ __forceinline__ float unpk_sum(ull a) {
    float lo, hi;
    asm("mov.b64 {%0, %1}, %2;" : "=f"(lo), "=f"(hi) : "l"(a));
    return lo + hi;
}
__device__ __forceinline__ float4 u2f4(ull x, ull z) {
    float4 f;
    asm("mov.b64 {%0, %1}, %2;" : "=f"(f.x), "=f"(f.y) : "l"(x));
    asm("mov.b64 {%0, %1}, %2;" : "=f"(f.z), "=f"(f.w) : "l"(z));
    return f;
}
__device__ __forceinline__ uint32_t s2u(const void* p) {
    return (uint32_t)__cvta_generic_to_shared(p);
}
__device__ __forceinline__ void bulk_store(void* gdst, uint32_t ssrc, uint32_t bytes) {
    asm volatile("cp.async.bulk.global.shared::cta.bulk_group [%0], [%1], %2;"
                 :: "l"(gdst), "r"(ssrc), "r"(bytes) : "memory");
}
__device__ __forceinline__ void fence_async() {
    asm volatile("fence.proxy.async.shared::cta;" ::: "memory");
}
__device__ __forceinline__ void cp16(uint32_t sdst, const void* gsrc, uint32_t sz) {
    asm volatile("cp.async.cg.shared.global [%0], [%1], 16, %2;"
                 :: "r"(sdst), "l"(gsrc), "r"(sz) : "memory");
}
__device__ __forceinline__ void cp_commit() {
    asm volatile("cp.async.commit_group;" ::: "memory");
}
__device__ __forceinline__ void cp_wait0() {
    asm volatile("cp.async.wait_group 0;" ::: "memory");
}

__global__ void __launch_bounds__(NTH, 1)
cwa_kernel(const float* __restrict__ q,
           const float* __restrict__ k,
           const float* __restrict__ v,
           float* __restrict__ out,    // [BH, SQ, DH]
           float* __restrict__ attn)   // [BH, SQ, SQ]
{
    extern __shared__ float sm[];
    float* sQ = sm + SM_Q;   // Q tile; reused as PV combine buffer
    float* sK = sm + SM_K;   // K tile; reused for V
    float* sS = sm + SM_S;   // 64 rows x SROW; row m offsets indexed [-4, 264)
    float* sZ = sm + SM_Z;   // 2048 zero floats

    const int tile = blockIdx.x;
    const int bh   = blockIdx.y;
    const int i0   = tile * MT;
    const int tid  = threadIdx.x;
    const int lane = tid & 31;
    const int w    = tid >> 5;           // 0..15

    const size_t base = (size_t)bh * SQ * DH;
    const size_t attn_base = (size_t)bh * SQ * SQ;
    const int jn0 = i0 - (WIN - 1);      // key j for smem key-row n: j = jn0 + n

    // ---- zero buffer + pre-zero the whole score surface ----
    {
        const float4 z4 = make_float4(0.f, 0.f, 0.f, 0.f);
        float4* zs = (float4*)sZ;
        for (int idx = tid; idx < 2048 / 4; idx += NTH)
            zs[idx] = z4;
        float4* ss4 = (float4*)sS;
        for (int idx = tid; idx < MT * SROW / 4; idx += NTH)
            ss4[idx] = z4;
    }
    // ---- Q tile via cp.async ----
    {
        const float4* qg = (const float4*)(q + base + (size_t)i0 * DH);
        for (int idx = tid; idx < MT * (DH / 4); idx += NTH)
            cp16(s2u((float4*)sQ + idx), qg + idx, 16);
    }
    // ---- K window via cp.async (zero-fill OOB via src_size=0) ----
    for (int idx = tid; idx < KRA * (DH / 4); idx += NTH) {
        int n = idx >> 4;
        int c = idx & 15;
        int j = jn0 + n;
        bool valid = (j >= 0 && j < SQ);
        const float* src = valid ? (k + base + (size_t)j * DH + c * 4) : (k + base);
        cp16(s2u(&sK[n * KPAD + c * 4]), src, valid ? 16u : 0u);
    }
    cp_commit();
    __syncthreads();    // sZ, sS zeros visible CTA-wide

    // ---- issue zero prefix/suffix bulk stores for all 64 rows NOW ----
    if (tid < MT) {
        const int m = tid;
        const int i = i0 + m;
        const int jlo = max(0, i - (WIN - 1));
        const int jstart4 = jlo & ~3;
        const int jend4 = (i + 4) & ~3;           // exclusive, multiple of 4
        float* dst = attn + attn_base + (size_t)i * SQ;
        const uint32_t zaddr = s2u(sZ);
        fence_async();
        const uint32_t pb = (uint32_t)jstart4 * 4u;
        if (pb) bulk_store(dst, zaddr, pb);
        const uint32_t sb = (uint32_t)(SQ - jend4) * 4u;
        if (sb) bulk_store(dst + jend4, zaddr, sb);
    }

    cp_wait0();
    __syncthreads();    // Q, K resident

    // ---- QK + fused register softmax: warp w -> rows m0..m0+3 ----
    const int m0 = w * 4;
    {
        ull acc[4][9];
        #pragma unroll
        for (int mi = 0; mi < 4; mi++)
            #pragma unroll
            for (int ni = 0; ni < 9; ni++)
                acc[mi][ni] = 0ULL;

        int nb[9];
        #pragma unroll
        for (int ni = 0; ni < 9; ni++)
            nb[ni] = (m0 + lane + 32 * ni) * KPAD;

        #pragma unroll 1
        for (int dc = 0; dc < DH / 4; dc++) {
            ulonglong2 q2[4];
            #pragma unroll
            for (int mi = 0; mi < 4; mi++)
                q2[mi] = *(const ulonglong2*)&sQ[(m0 + mi) * DH + dc * 4];
            #pragma unroll
            for (int ni = 0; ni < 9; ni++) {
                ulonglong2 k2 = *(const ulonglong2*)&sK[nb[ni] + dc * 4];
                #pragma unroll
                for (int mi = 0; mi < 4; mi++) {
                    ffma2(acc[mi][ni], q2[mi].x, k2.x);
                    ffma2(acc[mi][ni], q2[mi].y, k2.y);
                }
            }
        }

        // epilogue: per row, masked max + exp + sum in registers; store final p
        #pragma unroll
        for (int mi = 0; mi < 4; mi++) {
            const int m = m0 + mi;
            const int i = i0 + m;
            const int jlo = max(0, i - (WIN - 1));
            const int s = (jlo & ~3) - jn0;
            const int off_lo = jlo & 3;
            const int off_hi = i - (jlo & ~3);

            float sc[9];
            bool val[9];
            float mx = -1e30f;
            #pragma unroll
            for (int ni = 0; ni < 9; ni++) {
                const int off = m0 + lane + 32 * ni - s;
                sc[ni] = unpk_sum(acc[mi][ni]) * 0.125f;   // 1/temperature
                val[ni] = (off >= off_lo) && (off <= off_hi);
                if (val[ni]) mx = fmaxf(mx, sc[ni]);
            }
            #pragma unroll
            for (int o = 16; o; o >>= 1)
                mx = fmaxf(mx, __shfl_xor_sync(0xffffffffu, mx, o));

            float sum = 0.f;
            #pragma unroll
            for (int ni = 0; ni < 9; ni++) {
                float e = val[ni] ? __expf(sc[ni] - mx) : 0.f;
                sc[ni] = e;
                sum += e;
            }
            #pragma unroll
            for (int o = 16; o; o >>= 1)
                sum += __shfl_xor_sync(0xffffffffu, sum, o);

            const float inv = 1.f / sum;
            float* rp = sS + m * SROW + 4;
            #pragma unroll
            for (int ni = 0; ni < 9; ni++) {
                const int off = m0 + lane + 32 * ni - s;
                if (val[ni])
                    rp[off] = sc[ni] * inv;
            }
        }
    }
    __syncthreads();   // all QK reads of sK done; all p stores CTA-visible

    // ---- V via cp.async into sK ----
    for (int idx = tid; idx < KR * (DH / 4); idx += NTH) {
        int n = idx >> 4;
        int c = idx & 15;
        int j = jn0 + n;
        bool valid = (j >= 0 && j < SQ);
        const float* src = valid ? (v + base + (size_t)j * DH + c * 4) : (v + base);
        cp16(s2u(&sK[n * KPAD + c * 4]), src, valid ? 16u : 0u);
    }
    cp_commit();

    // ---- issue band bulk stores while V drains (p is final + visible) ----
    if (tid < MT) {
        const int m = tid;
        const int i = i0 + m;
        const int jlo = max(0, i - (WIN - 1));
        const int jstart4 = jlo & ~3;
        const int jend4 = (i + 4) & ~3;
        fence_async();
        bulk_store(attn + attn_base + (size_t)i * SQ + jstart4,
                   s2u(sS + m * SROW + 4),
                   (uint32_t)(jend4 - jstart4) * 4u);
    }

    cp_wait0();        // V resident
    __syncthreads();

    // ---- PV: thread owns 4 rows (grp) x 1 d-quad (dq) x half keys (kh) ----
    {
        const int dq  = tid & 15;         // d cols dq*4..dq*4+3
        const int grp = (tid >> 4) & 15;  // rows grp*4..grp*4+3
        const int kh  = tid >> 8;         // key half
        const int r0  = grp * 4;

        int sr[4];
        #pragma unroll
        for (int rr = 0; rr < 4; rr++)
            sr[rr] = (max(0, i0 + r0 + rr - (WIN - 1)) & ~3) - jn0;

        const int nbase = sr[3] - 4;            // ≡ 3 mod 4; aligned p4 loads
        const int nend  = r0 + 258;             // inclusive
        const int iters = (nend - nbase + 1) >> 2;
        const int ih    = (iters + 1) >> 1;
        const int itlo  = kh ? ih : 0;
        const int ithi  = kh ? iters : ih;

        const float* rp0 = sS + (r0 + 0) * SROW + 4 - sr[0];
        const float* rp1 = sS + (r0 + 1) * SROW + 4 - sr[1];
        const float* rp2 = sS + (r0 + 2) * SROW + 4 - sr[2];
        const float* rp3 = sS + (r0 + 3) * SROW + 4 - sr[3];

        ull ax[4], az[4];
        #pragma unroll
        for (int rr = 0; rr < 4; rr++) { ax[rr] = 0ULL; az[rr] = 0ULL; }

        #pragma unroll 1
        for (int it = itlo; it < ithi; it++) {
            const int n = nbase + 4 * it;
            const float4 p0 = *(const float4*)&rp0[n];
            const float4 p1 = *(const float4*)&rp1[n];
            const float4 p2 = *(const float4*)&rp2[n];
            const float4 p3 = *(const float4*)&rp3[n];
            #pragma unroll
            for (int c = 0; c < 4; c++) {
                ulonglong2 v2 = *(const ulonglong2*)&sK[(n + c) * KPAD + dq * 4];
                ull pc0 = pk2((&p0.x)[c]);
                ull pc1 = pk2((&p1.x)[c]);
                ull pc2 = pk2((&p2.x)[c]);
                ull pc3 = pk2((&p3.x)[c]);
                ffma2(ax[0], pc0, v2.x); ffma2(az[0], pc0, v2.y);
                ffma2(ax[1], pc1, v2.x); ffma2(az[1], pc1, v2.y);
                ffma2(ax[2], pc2, v2.x); ffma2(az[2], pc2, v2.y);
                ffma2(ax[3], pc3, v2.x); ffma2(az[3], pc3, v2.y);
            }
        }

        // combine halves through sQ (Q consumed; 64 rows x 64 d = 16KB)
        if (kh == 0) {
            #pragma unroll
            for (int rr = 0; rr < 4; rr++)
                *(float4*)&sQ[(r0 + rr) * DH + dq * 4] = u2f4(ax[rr], az[rr]);
        }
        __syncthreads();
        if (kh == 1) {
            #pragma unroll
            for (int rr = 0; rr < 4; rr++) {
                float4 part = *(const float4*)&sQ[(r0 + rr) * DH + dq * 4];
                float4 mine = u2f4(ax[rr], az[rr]);
                mine.x += part.x; mine.y += part.y;
                mine.z += part.z; mine.w += part.w;
                *(float4*)(out + base + (size_t)(i0 + r0 + rr) * DH + dq * 4) = mine;
            }
        }
    }

    // ---- ensure all bulk stores complete before kernel end ----
    asm volatile("cp.async.bulk.commit_group;" ::: "memory");
    asm volatile("cp.async.bulk.wait_group 0;" ::: "memory");
}

extern "C" void kernel_launch(void* const* d_in, const int* in_sizes, int n_in,
                              void* d_out, int out_size)
{
    const float* q = (const float*)d_in[0];
    const float* k = (const float*)d_in[1];
    const float* v = (const float*)d_in[2];

    const int BH = in_sizes[0] / (SQ * DH);   // 32

    float* out  = (float*)d_out;
    float* attn = out + (size_t)BH * SQ * DH;

    cudaFuncSetAttribute(cwa_kernel,
                         cudaFuncAttributeMaxDynamicSharedMemorySize,
                         SM_TOT * (int)sizeof(float));

    dim3 grid(SQ / MT, BH);
    cwa_kernel<<<grid, NTH, SM_TOT * sizeof(float)>>>(q, k, v, out, attn);
    (void)n_in; (void)out_size;
}